// round 9
// baseline (speedup 1.0000x reference)
#include <cuda_runtime.h>
#include <cuda_fp16.h>
#include <cstdint>

#define Bsz  4
#define Tseq 2048
#define Cemb 1024
#define NH   16
#define HD   64
#define NTOK (Bsz * Tseq)   // 8192

// ---------------------------------------------------------------------------
// Scratch (static device globals — no runtime allocation)
// ---------------------------------------------------------------------------
__device__ __half g_h[NTOK * Cemb];            // LN output (half)
__device__ __half g_qkv[NTOK * 3 * Cemb];      // QKV (half)
__device__ __half g_yh[NTOK * Cemb];           // attention out (half)
__device__ __half g_ffh[NTOK * 4 * Cemb];      // FF1 out (half)
__device__ __half g_wt_qkv[3 * Cemb * Cemb];   // transposed weights (half)
__device__ __half g_wt_proj[Cemb * Cemb];
__device__ __half g_wt_ff1[4 * Cemb * Cemb];
__device__ __half g_wt_ff2[Cemb * 4 * Cemb];

// ---------------------------------------------------------------------------
// Helpers
// ---------------------------------------------------------------------------
__device__ __forceinline__ uint32_t smem_u32(const void* p) {
    uint32_t a;
    asm("{ .reg .u64 t; cvta.to.shared.u64 t, %1; cvt.u32.u64 %0, t; }"
        : "=r"(a) : "l"(p));
    return a;
}
__device__ __forceinline__ uint32_t pack_h2(float a, float b) {
    __half2 h = __floats2half2_rn(a, b);
    return *(uint32_t*)&h;
}

#define CP16(sa, gp) \
    asm volatile("cp.async.cg.shared.global [%0], [%1], 16;" :: "r"(sa), "l"(gp))
#define CP_COMMIT() asm volatile("cp.async.commit_group;" ::: "memory")
#define CP_WAIT(n)  asm volatile("cp.async.wait_group %0;" :: "n"(n) : "memory")

#define LDSM4(R0, R1, R2, R3, ADDR) \
    asm volatile("ldmatrix.sync.aligned.m8n8.x4.shared.b16 {%0,%1,%2,%3}, [%4];" \
        : "=r"(R0), "=r"(R1), "=r"(R2), "=r"(R3) : "r"(ADDR))
#define LDSM4T(R0, R1, R2, R3, ADDR) \
    asm volatile("ldmatrix.sync.aligned.m8n8.x4.trans.shared.b16 {%0,%1,%2,%3}, [%4];" \
        : "=r"(R0), "=r"(R1), "=r"(R2), "=r"(R3) : "r"(ADDR))

__device__ __forceinline__ void mma16816(float* c, const uint32_t* a, const uint32_t* b) {
    asm volatile(
        "mma.sync.aligned.m16n8k16.row.col.f32.f16.f16.f32 "
        "{%0,%1,%2,%3}, {%4,%5,%6,%7}, {%8,%9}, {%0,%1,%2,%3};"
        : "+f"(c[0]), "+f"(c[1]), "+f"(c[2]), "+f"(c[3])
        : "r"(a[0]), "r"(a[1]), "r"(a[2]), "r"(a[3]), "r"(b[0]), "r"(b[1]));
}

// ---------------------------------------------------------------------------
// Weight transpose: W[K,N] (f32) -> Wt[N,K] (half)
// ---------------------------------------------------------------------------
__global__ __launch_bounds__(256) void transpose_kernel(
    const float* __restrict__ W, __half* __restrict__ Wt, int K, int N)
{
    __shared__ float t[32][33];
    int k0 = blockIdx.x * 32, n0 = blockIdx.y * 32;
    int tx = threadIdx.x, ty = threadIdx.y;
#pragma unroll
    for (int i = 0; i < 4; i++)
        t[ty + i * 8][tx] = W[(size_t)(k0 + ty + i * 8) * N + n0 + tx];
    __syncthreads();
#pragma unroll
    for (int i = 0; i < 4; i++)
        Wt[(size_t)(n0 + ty + i * 8) * K + k0 + tx] = __float2half_rn(t[tx][ty + i * 8]);
}

// ---------------------------------------------------------------------------
// LayerNorm: f32 in, half out
// ---------------------------------------------------------------------------
__global__ __launch_bounds__(256) void ln_kernel(
    const float* __restrict__ x, const float* __restrict__ w,
    const float* __restrict__ b, __half* __restrict__ out)
{
    __shared__ float red[64];
    int row = blockIdx.x;
    int tid = threadIdx.x;
    const float* xr = x + (size_t)row * Cemb;

    float v[4];
    float s = 0.f, s2 = 0.f;
#pragma unroll
    for (int i = 0; i < 4; i++) {
        v[i] = xr[i * 256 + tid];
        s  += v[i];
        s2 += v[i] * v[i];
    }
#pragma unroll
    for (int o = 16; o; o >>= 1) {
        s  += __shfl_xor_sync(~0u, s,  o);
        s2 += __shfl_xor_sync(~0u, s2, o);
    }
    int warp = tid >> 5, lane = tid & 31;
    if (lane == 0) { red[warp] = s; red[warp + 8] = s2; }
    __syncthreads();
    if (tid < 32) {
        float a  = (tid < 8) ? red[tid]     : 0.f;
        float a2 = (tid < 8) ? red[tid + 8] : 0.f;
#pragma unroll
        for (int o = 4; o; o >>= 1) {
            a  += __shfl_xor_sync(~0u, a,  o);
            a2 += __shfl_xor_sync(~0u, a2, o);
        }
        if (tid == 0) { red[0] = a; red[1] = a2; }
    }
    __syncthreads();
    float mean = red[0] * (1.f / Cemb);
    float var  = red[1] * (1.f / Cemb) - mean * mean;
    float rstd = rsqrtf(var + 1e-5f);
#pragma unroll
    for (int i = 0; i < 4; i++) {
        int c = i * 256 + tid;
        out[(size_t)row * Cemb + c] = __float2half_rn((v[i] - mean) * rstd * w[c] + b[c]);
    }
}

// ---------------------------------------------------------------------------
// fp16 mma.sync GEMM: C = A[M,K] @ Bt[N,K]^T + bias (+relu) (+resid)
// BM=128, BN=128, BK=64. 128 threads = 4 warps (2M x 2N), warp tile 64x64
// = 4x8 m16n8k16 (32 MMA / 8 LDSM per k16-step). 3-stage cp.async.
// ---------------------------------------------------------------------------
#define SSTRH 72
#define STAGE_B (128 * SSTRH * 2)   // 18432 bytes
#define NST 3
#define GSMEM_BYTES (2 * NST * STAGE_B)  // 110592

__global__ __launch_bounds__(128) void hgemm_kernel(
    const __half* __restrict__ A, const __half* __restrict__ Bt,
    const float* __restrict__ bias, const float* resid,
    float* Cf, __half* Ch, int M, int N, int K, int relu)
{
    extern __shared__ char smem[];
    const uint32_t sbA = smem_u32(smem);
    const uint32_t sbB = sbA + NST * STAGE_B;

    int tid = threadIdx.x, wid = tid >> 5, lane = tid & 31;
    int warp_m = wid >> 1, warp_n = wid & 1;   // 2 x 2
    int g = lane >> 2, t = lane & 3;
    int n0 = blockIdx.x * 128, m0 = blockIdx.y * 128;

    int la  = lane & 15, ka8 = (lane >> 4) * 8;
    int lb  = lane & 7;
    int quad = lane >> 3;
    int jsel = quad >> 1, kb8 = (quad & 1) * 8;

    float acc[4][8][4];
#pragma unroll
    for (int i = 0; i < 4; i++)
#pragma unroll
        for (int j = 0; j < 8; j++)
#pragma unroll
            for (int q = 0; q < 4; q++) acc[i][j][q] = 0.f;

    const int nk = K >> 6;

    auto load_stage = [&](int s, int kc) {
        int k0 = kc << 6;
#pragma unroll
        for (int i = 0; i < 8; i++) {
            int idx = tid + i * 128;
            int r = idx >> 3, c = idx & 7;
            uint32_t so = (uint32_t)(r * 144 + c * 16);
            CP16(sbA + s * STAGE_B + so, A  + (size_t)(m0 + r) * K + k0 + c * 8);
            CP16(sbB + s * STAGE_B + so, Bt + (size_t)(n0 + r) * K + k0 + c * 8);
        }
        CP_COMMIT();
    };

    load_stage(0, 0);
    load_stage(1, 1);
    load_stage(2, 2);

    for (int kc = 0; kc < nk; kc++) {
        int buf = kc % NST;
        CP_WAIT(2);
        __syncthreads();

        uint32_t Ab = sbA + buf * STAGE_B;
        uint32_t Bb = sbB + buf * STAGE_B;
#pragma unroll
        for (int ks = 0; ks < 4; ks++) {
            int kk = ks * 16;
            uint32_t a[4][4], bf[8][2];
#pragma unroll
            for (int i = 0; i < 4; i++)
                LDSM4(a[i][0], a[i][1], a[i][2], a[i][3],
                      Ab + (uint32_t)((warp_m * 64 + i * 16 + la) * 144 + (kk + ka8) * 2));
#pragma unroll
            for (int jp = 0; jp < 4; jp++) {
                uint32_t r0, r1, r2, r3;
                LDSM4(r0, r1, r2, r3,
                      Bb + (uint32_t)((warp_n * 64 + (jp * 2 + jsel) * 8 + lb) * 144
                                      + (kk + kb8) * 2));
                bf[jp * 2][0] = r0; bf[jp * 2][1] = r1;
                bf[jp * 2 + 1][0] = r2; bf[jp * 2 + 1][1] = r3;
            }
#pragma unroll
            for (int i = 0; i < 4; i++)
#pragma unroll
                for (int j = 0; j < 8; j++)
                    mma16816(acc[i][j], a[i], bf[j]);
        }
        __syncthreads();
        if (kc + NST < nk) load_stage(buf, kc + NST);
        else CP_COMMIT();
    }

#pragma unroll
    for (int i = 0; i < 4; i++) {
        int m = m0 + warp_m * 64 + i * 16 + g;
#pragma unroll
        for (int j = 0; j < 8; j++) {
            int n = n0 + warp_n * 64 + j * 8 + t * 2;
            float b0 = bias[n], b1 = bias[n + 1];
            float v0 = acc[i][j][0] + b0, v1 = acc[i][j][1] + b1;
            float v2 = acc[i][j][2] + b0, v3 = acc[i][j][3] + b1;
            if (relu) {
                v0 = fmaxf(v0, 0.f); v1 = fmaxf(v1, 0.f);
                v2 = fmaxf(v2, 0.f); v3 = fmaxf(v3, 0.f);
            }
            size_t go0 = (size_t)m * N + n;
            size_t go1 = (size_t)(m + 8) * N + n;
            if (Ch) {
                *(__half2*)(Ch + go0) = __floats2half2_rn(v0, v1);
                *(__half2*)(Ch + go1) = __floats2half2_rn(v2, v3);
            } else {
                if (resid) {
                    float2 r0 = *(const float2*)(resid + go0);
                    float2 r1 = *(const float2*)(resid + go1);
                    v0 += r0.x; v1 += r0.y; v2 += r1.x; v3 += r1.y;
                }
                *(float2*)(Cf + go0) = make_float2(v0, v1);
                *(float2*)(Cf + go1) = make_float2(v2, v3);
            }
        }
    }
}

// ---------------------------------------------------------------------------
// Flash attention (R8 shape: BR=BC=64, register S->P repack, reversed grid)
// ---------------------------------------------------------------------------
#define FST 72
#define FLASH_SMEM (3 * 64 * FST * 2)   // 27648

__global__ void __launch_bounds__(128) flash_kernel(
    const __half* __restrict__ qkv, __half* __restrict__ y)
{
    extern __shared__ __half fsm[];
    const uint32_t sKs = smem_u32(fsm);
    const uint32_t sVs = sKs + 64 * 144;
    const uint32_t sQs = sKs + 2 * 64 * 144;

    int tid = threadIdx.x, w = tid >> 5, lane = tid & 31;
    int g = lane >> 2, t = lane & 3;
    int la = lane & 15, ka8 = (lane >> 4) * 8;
    int lb = lane & 7;
    int quad = lane >> 3;
    int jsel = quad >> 1, kb8 = (quad & 1) * 8;
    int vrow = (quad & 1) * 8 + lb;

    int qt = (gridDim.x - 1) - blockIdx.x;   // heavy blocks first
    int h = blockIdx.y, b = blockIdx.z;
    int q0 = qt * 64;
    const __half* base = qkv + (size_t)b * Tseq * 3072;

    // Q tile via cp.async
#pragma unroll
    for (int i = 0; i < 4; i++) {
        int idx = tid + i * 128;
        int r = idx >> 3, c = idx & 7;
        CP16(sQs + (uint32_t)(r * 144 + c * 16),
             base + (size_t)(q0 + r) * 3072 + h * HD + c * 8);
    }
    CP_COMMIT(); CP_WAIT(0);
    __syncthreads();

    uint32_t qa[4][4];
#pragma unroll
    for (int ks = 0; ks < 4; ks++)
        LDSM4(qa[ks][0], qa[ks][1], qa[ks][2], qa[ks][3],
              sQs + (uint32_t)((w * 16 + la) * 144 + (ks * 16 + ka8) * 2));

    float m0 = -1e30f, l0 = 0.f, m1 = -1e30f, l1 = 0.f;
    float o[8][4];
#pragma unroll
    for (int j = 0; j < 8; j++)
#pragma unroll
        for (int q = 0; q < 4; q++) o[j][q] = 0.f;

    const int qrow0 = q0 + w * 16 + g;

    for (int kt = 0; kt <= qt; kt++) {
        int k0 = kt * 64;
        __syncthreads();
#pragma unroll
        for (int i = 0; i < 4; i++) {
            int idx = tid + i * 128;
            int r = idx >> 3, c = idx & 7;
            uint32_t so = (uint32_t)(r * 144 + c * 16);
            const __half* kr = base + (size_t)(k0 + r) * 3072 + Cemb + h * HD + c * 8;
            CP16(sKs + so, kr);
            CP16(sVs + so, kr + Cemb);
        }
        CP_COMMIT(); CP_WAIT(0);
        __syncthreads();

        // S = Q @ K^T
        float s[8][4];
#pragma unroll
        for (int j = 0; j < 8; j++)
#pragma unroll
            for (int q = 0; q < 4; q++) s[j][q] = 0.f;
#pragma unroll
        for (int ks = 0; ks < 4; ks++) {
            int kk = ks * 16;
            uint32_t kb[8][2];
#pragma unroll
            for (int jp = 0; jp < 4; jp++) {
                uint32_t r0, r1, r2, r3;
                LDSM4(r0, r1, r2, r3,
                      sKs + (uint32_t)(((jp * 2 + jsel) * 8 + lb) * 144 + (kk + kb8) * 2));
                kb[jp * 2][0] = r0; kb[jp * 2][1] = r1;
                kb[jp * 2 + 1][0] = r2; kb[jp * 2 + 1][1] = r3;
            }
#pragma unroll
            for (int j = 0; j < 8; j++)
                mma16816(s[j], qa[ks], kb[j]);
        }

        // mask + online softmax (scale 1/sqrt(Cemb) = 1/32)
        const float sc = 0.03125f;
        float mt0 = -1e30f, mt1 = -1e30f;
        bool diag = (kt == qt);
#pragma unroll
        for (int j = 0; j < 8; j++) {
            int cb = k0 + j * 8 + t * 2;
            if (diag) {
                s[j][0] = (cb     <= qrow0)     ? s[j][0] * sc : -1e30f;
                s[j][1] = (cb + 1 <= qrow0)     ? s[j][1] * sc : -1e30f;
                s[j][2] = (cb     <= qrow0 + 8) ? s[j][2] * sc : -1e30f;
                s[j][3] = (cb + 1 <= qrow0 + 8) ? s[j][3] * sc : -1e30f;
            } else {
                s[j][0] *= sc; s[j][1] *= sc; s[j][2] *= sc; s[j][3] *= sc;
            }
            mt0 = fmaxf(mt0, fmaxf(s[j][0], s[j][1]));
            mt1 = fmaxf(mt1, fmaxf(s[j][2], s[j][3]));
        }
        mt0 = fmaxf(mt0, __shfl_xor_sync(~0u, mt0, 1));
        mt0 = fmaxf(mt0, __shfl_xor_sync(~0u, mt0, 2));
        mt1 = fmaxf(mt1, __shfl_xor_sync(~0u, mt1, 1));
        mt1 = fmaxf(mt1, __shfl_xor_sync(~0u, mt1, 2));

        float mn0 = fmaxf(m0, mt0), mn1 = fmaxf(m1, mt1);
        float cr0 = __expf(m0 - mn0), cr1 = __expf(m1 - mn1);
        float ls0 = 0.f, ls1 = 0.f;
#pragma unroll
        for (int j = 0; j < 8; j++) {
            s[j][0] = __expf(s[j][0] - mn0);
            s[j][1] = __expf(s[j][1] - mn0);
            s[j][2] = __expf(s[j][2] - mn1);
            s[j][3] = __expf(s[j][3] - mn1);
            ls0 += s[j][0] + s[j][1];
            ls1 += s[j][2] + s[j][3];
        }
        ls0 += __shfl_xor_sync(~0u, ls0, 1);
        ls0 += __shfl_xor_sync(~0u, ls0, 2);
        ls1 += __shfl_xor_sync(~0u, ls1, 1);
        ls1 += __shfl_xor_sync(~0u, ls1, 2);
        l0 = l0 * cr0 + ls0;
        l1 = l1 * cr1 + ls1;
        m0 = mn0; m1 = mn1;
#pragma unroll
        for (int j = 0; j < 8; j++) {
            o[j][0] *= cr0; o[j][1] *= cr0;
            o[j][2] *= cr1; o[j][3] *= cr1;
        }

        // O += P @ V  — P packed from S registers (C-frag == A-frag layout)
#pragma unroll
        for (int ks = 0; ks < 4; ks++) {
            int kk = ks * 16;
            uint32_t pa[4];
            pa[0] = pack_h2(s[2 * ks][0],     s[2 * ks][1]);
            pa[1] = pack_h2(s[2 * ks][2],     s[2 * ks][3]);
            pa[2] = pack_h2(s[2 * ks + 1][0], s[2 * ks + 1][1]);
            pa[3] = pack_h2(s[2 * ks + 1][2], s[2 * ks + 1][3]);
            uint32_t vb[8][2];
#pragma unroll
            for (int jp = 0; jp < 4; jp++) {
                uint32_t r0, r1, r2, r3;
                LDSM4T(r0, r1, r2, r3,
                       sVs + (uint32_t)((kk + vrow) * 144 + (jp * 2 + jsel) * 16));
                vb[jp * 2][0] = r0; vb[jp * 2][1] = r1;
                vb[jp * 2 + 1][0] = r2; vb[jp * 2 + 1][1] = r3;
            }
#pragma unroll
            for (int j = 0; j < 8; j++)
                mma16816(o[j], pa, vb[j]);
        }
    }

    float il0 = 1.f / l0, il1 = 1.f / l1;
#pragma unroll
    for (int j = 0; j < 8; j++) {
        int col = h * HD + j * 8 + t * 2;
        size_t r0 = (size_t)(b * Tseq + qrow0) * Cemb + col;
        size_t r1 = (size_t)(b * Tseq + qrow0 + 8) * Cemb + col;
        *(__half2*)(y + r0) = __floats2half2_rn(o[j][0] * il0, o[j][1] * il0);
        *(__half2*)(y + r1) = __floats2half2_rn(o[j][2] * il1, o[j][3] * il1);
    }
}

// ---------------------------------------------------------------------------
// Launch
// ---------------------------------------------------------------------------
extern "C" void kernel_launch(void* const* d_in, const int* in_sizes, int n_in,
                              void* d_out, int out_size)
{
    (void)in_sizes; (void)n_in; (void)out_size;
    const float* x      = (const float*)d_in[0];
    const float* ln1_w  = (const float*)d_in[1];
    const float* ln1_b  = (const float*)d_in[2];
    const float* qkv_w  = (const float*)d_in[3];
    const float* qkv_b  = (const float*)d_in[4];
    const float* proj_w = (const float*)d_in[5];
    const float* proj_b = (const float*)d_in[6];
    const float* ln2_w  = (const float*)d_in[7];
    const float* ln2_b  = (const float*)d_in[8];
    const float* ff_w1  = (const float*)d_in[9];
    const float* ff_b1  = (const float*)d_in[10];
    const float* ff_w2  = (const float*)d_in[11];
    const float* ff_b2  = (const float*)d_in[12];
    float* out = (float*)d_out;

    __half *ph, *pqkv, *py, *pff, *twq, *twp, *tw1, *tw2;
    cudaGetSymbolAddress((void**)&ph,   g_h);
    cudaGetSymbolAddress((void**)&pqkv, g_qkv);
    cudaGetSymbolAddress((void**)&py,   g_yh);
    cudaGetSymbolAddress((void**)&pff,  g_ffh);
    cudaGetSymbolAddress((void**)&twq,  g_wt_qkv);
    cudaGetSymbolAddress((void**)&twp,  g_wt_proj);
    cudaGetSymbolAddress((void**)&tw1,  g_wt_ff1);
    cudaGetSymbolAddress((void**)&tw2,  g_wt_ff2);

    cudaFuncSetAttribute(hgemm_kernel,
                         cudaFuncAttributeMaxDynamicSharedMemorySize, GSMEM_BYTES);
    cudaFuncSetAttribute(flash_kernel,
                         cudaFuncAttributeMaxDynamicSharedMemorySize, FLASH_SMEM);

    dim3 tb(32, 8);
    transpose_kernel<<<dim3(Cemb / 32, 3 * Cemb / 32), tb>>>(qkv_w, twq, Cemb, 3 * Cemb);
    transpose_kernel<<<dim3(Cemb / 32, Cemb / 32),     tb>>>(proj_w, twp, Cemb, Cemb);
    transpose_kernel<<<dim3(Cemb / 32, 4 * Cemb / 32), tb>>>(ff_w1, tw1, Cemb, 4 * Cemb);
    transpose_kernel<<<dim3(4 * Cemb / 32, Cemb / 32), tb>>>(ff_w2, tw2, 4 * Cemb, Cemb);

    // 1) h = LN1(x)
    ln_kernel<<<NTOK, 256>>>(x, ln1_w, ln1_b, ph);
    // 2) qkv = h @ qkv_w + qkv_b  (half out)
    hgemm_kernel<<<dim3(3072 / 128, NTOK / 128), 128, GSMEM_BYTES>>>(
        ph, twq, qkv_b, nullptr, nullptr, pqkv, NTOK, 3072, 1024, 0);
    // 3) y = attention(q, k, v)  (half out)
    flash_kernel<<<dim3(Tseq / 64, NH, Bsz), 128, FLASH_SMEM>>>(pqkv, py);
    // 4) x2 = x + y @ proj_w + proj_b  (float out)
    hgemm_kernel<<<dim3(1024 / 128, NTOK / 128), 128, GSMEM_BYTES>>>(
        py, twp, proj_b, x, out, nullptr, NTOK, 1024, 1024, 0);
    // 5) h2 = LN2(x2)
    ln_kernel<<<NTOK, 256>>>(out, ln2_w, ln2_b, ph);
    // 6) ff = relu(h2 @ ff_w1 + ff_b1)  (half out)
    hgemm_kernel<<<dim3(4096 / 128, NTOK / 128), 128, GSMEM_BYTES>>>(
        ph, tw1, ff_b1, nullptr, nullptr, pff, NTOK, 4096, 1024, 1);
    // 7) out = x2 + ff @ ff_w2 + ff_b2  (float out)
    hgemm_kernel<<<dim3(1024 / 128, NTOK / 128), 128, GSMEM_BYTES>>>(
        pff, tw2, ff_b2, out, out, nullptr, NTOK, 1024, 4096, 0);
}

// round 10
// speedup vs baseline: 1.0247x; 1.0247x over previous
#include <cuda_runtime.h>
#include <cuda_fp16.h>
#include <cstdint>

#define Bsz  4
#define Tseq 2048
#define Cemb 1024
#define NH   16
#define HD   64
#define NTOK (Bsz * Tseq)   // 8192

// ---------------------------------------------------------------------------
// Scratch (static device globals — no runtime allocation)
// ---------------------------------------------------------------------------
__device__ __half g_h[NTOK * Cemb];            // LN output (half)
__device__ __half g_qkv[NTOK * 3 * Cemb];      // QKV (half)
__device__ __half g_yh[NTOK * Cemb];           // attention out (half)
__device__ __half g_ffh[NTOK * 4 * Cemb];      // FF1 out (half)
__device__ __half g_wt_qkv[3 * Cemb * Cemb];   // transposed weights (half)
__device__ __half g_wt_proj[Cemb * Cemb];
__device__ __half g_wt_ff1[4 * Cemb * Cemb];
__device__ __half g_wt_ff2[Cemb * 4 * Cemb];

// ---------------------------------------------------------------------------
// Helpers
// ---------------------------------------------------------------------------
__device__ __forceinline__ uint32_t smem_u32(const void* p) {
    uint32_t a;
    asm("{ .reg .u64 t; cvta.to.shared.u64 t, %1; cvt.u32.u64 %0, t; }"
        : "=r"(a) : "l"(p));
    return a;
}
__device__ __forceinline__ uint32_t pack_h2(float a, float b) {
    __half2 h = __floats2half2_rn(a, b);
    return *(uint32_t*)&h;
}

#define CP16(sa, gp) \
    asm volatile("cp.async.cg.shared.global [%0], [%1], 16;" :: "r"(sa), "l"(gp))
#define CP_COMMIT() asm volatile("cp.async.commit_group;" ::: "memory")
#define CP_WAIT(n)  asm volatile("cp.async.wait_group %0;" :: "n"(n) : "memory")

#define LDSM4(R0, R1, R2, R3, ADDR) \
    asm volatile("ldmatrix.sync.aligned.m8n8.x4.shared.b16 {%0,%1,%2,%3}, [%4];" \
        : "=r"(R0), "=r"(R1), "=r"(R2), "=r"(R3) : "r"(ADDR))
#define LDSM4T(R0, R1, R2, R3, ADDR) \
    asm volatile("ldmatrix.sync.aligned.m8n8.x4.trans.shared.b16 {%0,%1,%2,%3}, [%4];" \
        : "=r"(R0), "=r"(R1), "=r"(R2), "=r"(R3) : "r"(ADDR))

__device__ __forceinline__ void mma16816(float* c, const uint32_t* a, const uint32_t* b) {
    asm volatile(
        "mma.sync.aligned.m16n8k16.row.col.f32.f16.f16.f32 "
        "{%0,%1,%2,%3}, {%4,%5,%6,%7}, {%8,%9}, {%0,%1,%2,%3};"
        : "+f"(c[0]), "+f"(c[1]), "+f"(c[2]), "+f"(c[3])
        : "r"(a[0]), "r"(a[1]), "r"(a[2]), "r"(a[3]), "r"(b[0]), "r"(b[1]));
}

// ---------------------------------------------------------------------------
// Weight transpose: W[K,N] (f32) -> Wt[N,K] (half)
// ---------------------------------------------------------------------------
__global__ __launch_bounds__(256) void transpose_kernel(
    const float* __restrict__ W, __half* __restrict__ Wt, int K, int N)
{
    __shared__ float t[32][33];
    int k0 = blockIdx.x * 32, n0 = blockIdx.y * 32;
    int tx = threadIdx.x, ty = threadIdx.y;
#pragma unroll
    for (int i = 0; i < 4; i++)
        t[ty + i * 8][tx] = W[(size_t)(k0 + ty + i * 8) * N + n0 + tx];
    __syncthreads();
#pragma unroll
    for (int i = 0; i < 4; i++)
        Wt[(size_t)(n0 + ty + i * 8) * K + k0 + tx] = __float2half_rn(t[tx][ty + i * 8]);
}

// ---------------------------------------------------------------------------
// LayerNorm: f32 in, half out
// ---------------------------------------------------------------------------
__global__ __launch_bounds__(256) void ln_kernel(
    const float* __restrict__ x, const float* __restrict__ w,
    const float* __restrict__ b, __half* __restrict__ out)
{
    __shared__ float red[64];
    int row = blockIdx.x;
    int tid = threadIdx.x;
    const float* xr = x + (size_t)row * Cemb;

    float v[4];
    float s = 0.f, s2 = 0.f;
#pragma unroll
    for (int i = 0; i < 4; i++) {
        v[i] = xr[i * 256 + tid];
        s  += v[i];
        s2 += v[i] * v[i];
    }
#pragma unroll
    for (int o = 16; o; o >>= 1) {
        s  += __shfl_xor_sync(~0u, s,  o);
        s2 += __shfl_xor_sync(~0u, s2, o);
    }
    int warp = tid >> 5, lane = tid & 31;
    if (lane == 0) { red[warp] = s; red[warp + 8] = s2; }
    __syncthreads();
    if (tid < 32) {
        float a  = (tid < 8) ? red[tid]     : 0.f;
        float a2 = (tid < 8) ? red[tid + 8] : 0.f;
#pragma unroll
        for (int o = 4; o; o >>= 1) {
            a  += __shfl_xor_sync(~0u, a,  o);
            a2 += __shfl_xor_sync(~0u, a2, o);
        }
        if (tid == 0) { red[0] = a; red[1] = a2; }
    }
    __syncthreads();
    float mean = red[0] * (1.f / Cemb);
    float var  = red[1] * (1.f / Cemb) - mean * mean;
    float rstd = rsqrtf(var + 1e-5f);
#pragma unroll
    for (int i = 0; i < 4; i++) {
        int c = i * 256 + tid;
        out[(size_t)row * Cemb + c] = __float2half_rn((v[i] - mean) * rstd * w[c] + b[c]);
    }
}

// ---------------------------------------------------------------------------
// fp16 mma.sync GEMM (R8 config: 256 threads, 8 warps 2Mx4N, 64x32 warp tile)
// ---------------------------------------------------------------------------
#define SSTRH 72
#define STAGE_B (128 * SSTRH * 2)   // 18432 bytes
#define NST 3
#define GSMEM_BYTES (2 * NST * STAGE_B)  // 110592

__global__ __launch_bounds__(256) void hgemm_kernel(
    const __half* __restrict__ A, const __half* __restrict__ Bt,
    const float* __restrict__ bias, const float* resid,
    float* Cf, __half* Ch, int M, int N, int K, int relu)
{
    extern __shared__ char smem[];
    const uint32_t sbA = smem_u32(smem);
    const uint32_t sbB = sbA + NST * STAGE_B;

    int tid = threadIdx.x, wid = tid >> 5, lane = tid & 31;
    int warp_m = wid >> 2, warp_n = wid & 3;
    int g = lane >> 2, t = lane & 3;
    int n0 = blockIdx.x * 128, m0 = blockIdx.y * 128;

    int la  = lane & 15, ka8 = (lane >> 4) * 8;
    int lb  = lane & 7;
    int quad = lane >> 3;
    int jsel = quad >> 1, kb8 = (quad & 1) * 8;

    float acc[4][4][4];
#pragma unroll
    for (int i = 0; i < 4; i++)
#pragma unroll
        for (int j = 0; j < 4; j++)
#pragma unroll
            for (int q = 0; q < 4; q++) acc[i][j][q] = 0.f;

    const int nk = K >> 6;

    auto load_stage = [&](int s, int kc) {
        int k0 = kc << 6;
#pragma unroll
        for (int i = 0; i < 4; i++) {
            int idx = tid + i * 256;
            int r = idx >> 3, c = idx & 7;
            uint32_t so = (uint32_t)(r * 144 + c * 16);
            CP16(sbA + s * STAGE_B + so, A  + (size_t)(m0 + r) * K + k0 + c * 8);
            CP16(sbB + s * STAGE_B + so, Bt + (size_t)(n0 + r) * K + k0 + c * 8);
        }
        CP_COMMIT();
    };

    load_stage(0, 0);
    load_stage(1, 1);
    load_stage(2, 2);

    for (int kc = 0; kc < nk; kc++) {
        int buf = kc % NST;
        CP_WAIT(2);
        __syncthreads();

        uint32_t Ab = sbA + buf * STAGE_B;
        uint32_t Bb = sbB + buf * STAGE_B;
#pragma unroll
        for (int ks = 0; ks < 4; ks++) {
            int kk = ks * 16;
            uint32_t a[4][4], bf[4][2];
#pragma unroll
            for (int i = 0; i < 4; i++)
                LDSM4(a[i][0], a[i][1], a[i][2], a[i][3],
                      Ab + (uint32_t)((warp_m * 64 + i * 16 + la) * 144 + (kk + ka8) * 2));
#pragma unroll
            for (int jp = 0; jp < 2; jp++) {
                uint32_t r0, r1, r2, r3;
                LDSM4(r0, r1, r2, r3,
                      Bb + (uint32_t)((warp_n * 32 + (jp * 2 + jsel) * 8 + lb) * 144
                                      + (kk + kb8) * 2));
                bf[jp * 2][0] = r0; bf[jp * 2][1] = r1;
                bf[jp * 2 + 1][0] = r2; bf[jp * 2 + 1][1] = r3;
            }
#pragma unroll
            for (int i = 0; i < 4; i++)
#pragma unroll
                for (int j = 0; j < 4; j++)
                    mma16816(acc[i][j], a[i], bf[j]);
        }
        __syncthreads();
        if (kc + NST < nk) load_stage(buf, kc + NST);
        else CP_COMMIT();
    }

#pragma unroll
    for (int i = 0; i < 4; i++) {
        int m = m0 + warp_m * 64 + i * 16 + g;
#pragma unroll
        for (int j = 0; j < 4; j++) {
            int n = n0 + warp_n * 32 + j * 8 + t * 2;
            float b0 = bias[n], b1 = bias[n + 1];
            float v0 = acc[i][j][0] + b0, v1 = acc[i][j][1] + b1;
            float v2 = acc[i][j][2] + b0, v3 = acc[i][j][3] + b1;
            if (relu) {
                v0 = fmaxf(v0, 0.f); v1 = fmaxf(v1, 0.f);
                v2 = fmaxf(v2, 0.f); v3 = fmaxf(v3, 0.f);
            }
            size_t go0 = (size_t)m * N + n;
            size_t go1 = (size_t)(m + 8) * N + n;
            if (Ch) {
                *(__half2*)(Ch + go0) = __floats2half2_rn(v0, v1);
                *(__half2*)(Ch + go1) = __floats2half2_rn(v2, v3);
            } else {
                if (resid) {
                    float2 r0 = *(const float2*)(resid + go0);
                    float2 r1 = *(const float2*)(resid + go1);
                    v0 += r0.x; v1 += r0.y; v2 += r1.x; v3 += r1.y;
                }
                *(float2*)(Cf + go0) = make_float2(v0, v1);
                *(float2*)(Cf + go1) = make_float2(v2, v3);
            }
        }
    }
}

// ---------------------------------------------------------------------------
// Flash attention, fp16 mma, BR=BC=64, register S->P repack,
// log2-domain softmax: p = exp2(s*c - mn*c), c = (1/32)*log2(e).
// One FFMA + one EX2 per score element (was 3 FMA-ops + EX2).
// ---------------------------------------------------------------------------
#define FST 72
#define FLASH_SMEM (3 * 64 * FST * 2)   // 27648

__global__ void __launch_bounds__(128) flash_kernel(
    const __half* __restrict__ qkv, __half* __restrict__ y)
{
    extern __shared__ __half fsm[];
    const uint32_t sKs = smem_u32(fsm);
    const uint32_t sVs = sKs + 64 * 144;
    const uint32_t sQs = sKs + 2 * 64 * 144;

    int tid = threadIdx.x, w = tid >> 5, lane = tid & 31;
    int g = lane >> 2, t = lane & 3;
    int la = lane & 15, ka8 = (lane >> 4) * 8;
    int lb = lane & 7;
    int quad = lane >> 3;
    int jsel = quad >> 1, kb8 = (quad & 1) * 8;
    int vrow = (quad & 1) * 8 + lb;

    int qt = (gridDim.x - 1) - blockIdx.x;   // heavy blocks first
    int h = blockIdx.y, b = blockIdx.z;
    int q0 = qt * 64;
    const __half* base = qkv + (size_t)b * Tseq * 3072;

    // Q tile via cp.async
#pragma unroll
    for (int i = 0; i < 4; i++) {
        int idx = tid + i * 128;
        int r = idx >> 3, c = idx & 7;
        CP16(sQs + (uint32_t)(r * 144 + c * 16),
             base + (size_t)(q0 + r) * 3072 + h * HD + c * 8);
    }
    CP_COMMIT(); CP_WAIT(0);
    __syncthreads();

    uint32_t qa[4][4];
#pragma unroll
    for (int ks = 0; ks < 4; ks++)
        LDSM4(qa[ks][0], qa[ks][1], qa[ks][2], qa[ks][3],
              sQs + (uint32_t)((w * 16 + la) * 144 + (ks * 16 + ka8) * 2));

    // Softmax in log2 domain: scale*log2(e); all raw-score maxima, exponents
    // computed as exp2(s*C2 - m*C2).
    const float C2 = 0.03125f * 1.44269504088896f;

    float m0 = -1e30f, l0 = 0.f, m1 = -1e30f, l1 = 0.f;
    float o[8][4];
#pragma unroll
    for (int j = 0; j < 8; j++)
#pragma unroll
        for (int q = 0; q < 4; q++) o[j][q] = 0.f;

    const int qrow0 = q0 + w * 16 + g;

    for (int kt = 0; kt <= qt; kt++) {
        int k0 = kt * 64;
        __syncthreads();
#pragma unroll
        for (int i = 0; i < 4; i++) {
            int idx = tid + i * 128;
            int r = idx >> 3, c = idx & 7;
            uint32_t so = (uint32_t)(r * 144 + c * 16);
            const __half* kr = base + (size_t)(k0 + r) * 3072 + Cemb + h * HD + c * 8;
            CP16(sKs + so, kr);
            CP16(sVs + so, kr + Cemb);
        }
        CP_COMMIT(); CP_WAIT(0);
        __syncthreads();

        // S = Q @ K^T  (raw, unscaled)
        float s[8][4];
#pragma unroll
        for (int j = 0; j < 8; j++)
#pragma unroll
            for (int q = 0; q < 4; q++) s[j][q] = 0.f;
#pragma unroll
        for (int ks = 0; ks < 4; ks++) {
            int kk = ks * 16;
            uint32_t kb[8][2];
#pragma unroll
            for (int jp = 0; jp < 4; jp++) {
                uint32_t r0, r1, r2, r3;
                LDSM4(r0, r1, r2, r3,
                      sKs + (uint32_t)(((jp * 2 + jsel) * 8 + lb) * 144 + (kk + kb8) * 2));
                kb[jp * 2][0] = r0; kb[jp * 2][1] = r1;
                kb[jp * 2 + 1][0] = r2; kb[jp * 2 + 1][1] = r3;
            }
#pragma unroll
            for (int j = 0; j < 8; j++)
                mma16816(s[j], qa[ks], kb[j]);
        }

        // mask (diag tile only) + row max over raw scores
        float mt0 = -1e30f, mt1 = -1e30f;
        if (kt == qt) {
#pragma unroll
            for (int j = 0; j < 8; j++) {
                int cb = k0 + j * 8 + t * 2;
                s[j][0] = (cb     <= qrow0)     ? s[j][0] : -1e30f;
                s[j][1] = (cb + 1 <= qrow0)     ? s[j][1] : -1e30f;
                s[j][2] = (cb     <= qrow0 + 8) ? s[j][2] : -1e30f;
                s[j][3] = (cb + 1 <= qrow0 + 8) ? s[j][3] : -1e30f;
            }
        }
#pragma unroll
        for (int j = 0; j < 8; j++) {
            mt0 = fmaxf(mt0, fmaxf(s[j][0], s[j][1]));
            mt1 = fmaxf(mt1, fmaxf(s[j][2], s[j][3]));
        }
        mt0 = fmaxf(mt0, __shfl_xor_sync(~0u, mt0, 1));
        mt0 = fmaxf(mt0, __shfl_xor_sync(~0u, mt0, 2));
        mt1 = fmaxf(mt1, __shfl_xor_sync(~0u, mt1, 1));
        mt1 = fmaxf(mt1, __shfl_xor_sync(~0u, mt1, 2));

        float mn0 = fmaxf(m0, mt0), mn1 = fmaxf(m1, mt1);
        float cr0 = exp2f((m0 - mn0) * C2), cr1 = exp2f((m1 - mn1) * C2);
        float d0 = mn0 * C2, d1 = mn1 * C2;
        float ls0 = 0.f, ls1 = 0.f;
#pragma unroll
        for (int j = 0; j < 8; j++) {
            s[j][0] = exp2f(fmaf(s[j][0], C2, -d0));
            s[j][1] = exp2f(fmaf(s[j][1], C2, -d0));
            s[j][2] = exp2f(fmaf(s[j][2], C2, -d1));
            s[j][3] = exp2f(fmaf(s[j][3], C2, -d1));
            ls0 += s[j][0] + s[j][1];
            ls1 += s[j][2] + s[j][3];
        }
        ls0 += __shfl_xor_sync(~0u, ls0, 1);
        ls0 += __shfl_xor_sync(~0u, ls0, 2);
        ls1 += __shfl_xor_sync(~0u, ls1, 1);
        ls1 += __shfl_xor_sync(~0u, ls1, 2);
        l0 = l0 * cr0 + ls0;
        l1 = l1 * cr1 + ls1;
        m0 = mn0; m1 = mn1;
#pragma unroll
        for (int j = 0; j < 8; j++) {
            o[j][0] *= cr0; o[j][1] *= cr0;
            o[j][2] *= cr1; o[j][3] *= cr1;
        }

        // O += P @ V  — P packed from S registers (C-frag == A-frag layout)
#pragma unroll
        for (int ks = 0; ks < 4; ks++) {
            int kk = ks * 16;
            uint32_t pa[4];
            pa[0] = pack_h2(s[2 * ks][0],     s[2 * ks][1]);
            pa[1] = pack_h2(s[2 * ks][2],     s[2 * ks][3]);
            pa[2] = pack_h2(s[2 * ks + 1][0], s[2 * ks + 1][1]);
            pa[3] = pack_h2(s[2 * ks + 1][2], s[2 * ks + 1][3]);
            uint32_t vb[8][2];
#pragma unroll
            for (int jp = 0; jp < 4; jp++) {
                uint32_t r0, r1, r2, r3;
                LDSM4T(r0, r1, r2, r3,
                       sVs + (uint32_t)((kk + vrow) * 144 + (jp * 2 + jsel) * 16));
                vb[jp * 2][0] = r0; vb[jp * 2][1] = r1;
                vb[jp * 2 + 1][0] = r2; vb[jp * 2 + 1][1] = r3;
            }
#pragma unroll
            for (int j = 0; j < 8; j++)
                mma16816(o[j], pa, vb[j]);
        }
    }

    float il0 = 1.f / l0, il1 = 1.f / l1;
#pragma unroll
    for (int j = 0; j < 8; j++) {
        int col = h * HD + j * 8 + t * 2;
        size_t r0 = (size_t)(b * Tseq + qrow0) * Cemb + col;
        size_t r1 = (size_t)(b * Tseq + qrow0 + 8) * Cemb + col;
        *(__half2*)(y + r0) = __floats2half2_rn(o[j][0] * il0, o[j][1] * il0);
        *(__half2*)(y + r1) = __floats2half2_rn(o[j][2] * il1, o[j][3] * il1);
    }
}

// ---------------------------------------------------------------------------
// Launch
// ---------------------------------------------------------------------------
extern "C" void kernel_launch(void* const* d_in, const int* in_sizes, int n_in,
                              void* d_out, int out_size)
{
    (void)in_sizes; (void)n_in; (void)out_size;
    const float* x      = (const float*)d_in[0];
    const float* ln1_w  = (const float*)d_in[1];
    const float* ln1_b  = (const float*)d_in[2];
    const float* qkv_w  = (const float*)d_in[3];
    const float* qkv_b  = (const float*)d_in[4];
    const float* proj_w = (const float*)d_in[5];
    const float* proj_b = (const float*)d_in[6];
    const float* ln2_w  = (const float*)d_in[7];
    const float* ln2_b  = (const float*)d_in[8];
    const float* ff_w1  = (const float*)d_in[9];
    const float* ff_b1  = (const float*)d_in[10];
    const float* ff_w2  = (const float*)d_in[11];
    const float* ff_b2  = (const float*)d_in[12];
    float* out = (float*)d_out;

    __half *ph, *pqkv, *py, *pff, *twq, *twp, *tw1, *tw2;
    cudaGetSymbolAddress((void**)&ph,   g_h);
    cudaGetSymbolAddress((void**)&pqkv, g_qkv);
    cudaGetSymbolAddress((void**)&py,   g_yh);
    cudaGetSymbolAddress((void**)&pff,  g_ffh);
    cudaGetSymbolAddress((void**)&twq,  g_wt_qkv);
    cudaGetSymbolAddress((void**)&twp,  g_wt_proj);
    cudaGetSymbolAddress((void**)&tw1,  g_wt_ff1);
    cudaGetSymbolAddress((void**)&tw2,  g_wt_ff2);

    cudaFuncSetAttribute(hgemm_kernel,
                         cudaFuncAttributeMaxDynamicSharedMemorySize, GSMEM_BYTES);
    cudaFuncSetAttribute(flash_kernel,
                         cudaFuncAttributeMaxDynamicSharedMemorySize, FLASH_SMEM);

    dim3 tb(32, 8);
    transpose_kernel<<<dim3(Cemb / 32, 3 * Cemb / 32), tb>>>(qkv_w, twq, Cemb, 3 * Cemb);
    transpose_kernel<<<dim3(Cemb / 32, Cemb / 32),     tb>>>(proj_w, twp, Cemb, Cemb);
    transpose_kernel<<<dim3(Cemb / 32, 4 * Cemb / 32), tb>>>(ff_w1, tw1, Cemb, 4 * Cemb);
    transpose_kernel<<<dim3(4 * Cemb / 32, Cemb / 32), tb>>>(ff_w2, tw2, 4 * Cemb, Cemb);

    // 1) h = LN1(x)
    ln_kernel<<<NTOK, 256>>>(x, ln1_w, ln1_b, ph);
    // 2) qkv = h @ qkv_w + qkv_b  (half out)
    hgemm_kernel<<<dim3(3072 / 128, NTOK / 128), 256, GSMEM_BYTES>>>(
        ph, twq, qkv_b, nullptr, nullptr, pqkv, NTOK, 3072, 1024, 0);
    // 3) y = attention(q, k, v)  (half out)
    flash_kernel<<<dim3(Tseq / 64, NH, Bsz), 128, FLASH_SMEM>>>(pqkv, py);
    // 4) x2 = x + y @ proj_w + proj_b  (float out)
    hgemm_kernel<<<dim3(1024 / 128, NTOK / 128), 256, GSMEM_BYTES>>>(
        py, twp, proj_b, x, out, nullptr, NTOK, 1024, 1024, 0);
    // 5) h2 = LN2(x2)
    ln_kernel<<<NTOK, 256>>>(out, ln2_w, ln2_b, ph);
    // 6) ff = relu(h2 @ ff_w1 + ff_b1)  (half out)
    hgemm_kernel<<<dim3(4096 / 128, NTOK / 128), 256, GSMEM_BYTES>>>(
        ph, tw1, ff_b1, nullptr, nullptr, pff, NTOK, 4096, 1024, 1);
    // 7) out = x2 + ff @ ff_w2 + ff_b2  (float out)
    hgemm_kernel<<<dim3(1024 / 128, NTOK / 128), 256, GSMEM_BYTES>>>(
        pff, tw2, ff_b2, out, out, nullptr, NTOK, 1024, 4096, 0);
}